// round 5
// baseline (speedup 1.0000x reference)
#include <cuda_runtime.h>

// MeanAggregator with L2 temporal blocking.
// out[b,:] = mean_k table[neighs[b,k],:], B=50000, K=32, table 500000x128 f32.
//
// The unique gathered working set (~246MB) exceeds L2 (126MB), so a single
// pass refetches ~300MB from DRAM. Instead: 4 passes over the index list,
// pass p gathers only rows in segment [p*125K, (p+1)*125K) (64MB, L2-resident
// under evict_last). Accumulate raw sums into out; last pass scales by 1/32.

#define BATCH   50000
#define DEGREE  32
#define D_FEAT  128
#define WARPS_PER_BLOCK 8
#define THREADS (WARPS_PER_BLOCK * 32)
#define NSEG    4
#define SEG     (500000 / NSEG)

__device__ int g_idx_is64;

// int64 indices in [0,500000) have all odd 32-bit words == 0; int32 data has
// random values there (P(128 zeros) ~ 0).
__global__ void detect_idx_dtype(const unsigned int* __restrict__ n32)
{
    bool all_zero = true;
    #pragma unroll
    for (int i = 1; i < 256; i += 2) {
        if (n32[i] != 0u) { all_zero = false; break; }
    }
    g_idx_is64 = all_zero ? 1 : 0;
}

struct F8 { float v[8]; };

__device__ __forceinline__ F8 ldg_evict_last_v8(const float* p)
{
    F8 r;
    asm volatile(
        "ld.global.nc.L2::evict_last.v8.b32 {%0,%1,%2,%3,%4,%5,%6,%7}, [%8];"
        : "=f"(r.v[0]), "=f"(r.v[1]), "=f"(r.v[2]), "=f"(r.v[3]),
          "=f"(r.v[4]), "=f"(r.v[5]), "=f"(r.v[6]), "=f"(r.v[7])
        : "l"(p));
    return r;
}

__global__ __launch_bounds__(THREADS)
void mean_agg_pass(const void* __restrict__ neighs_raw,
                   const float* __restrict__ table,   // [500000, 128] f32
                   float* __restrict__ out,           // [50000, 128] f32 (raw sums until last pass)
                   int seg_lo, int seg_hi, int first, int last)
{
    const int warp = (blockIdx.x * THREADS + threadIdx.x) >> 5;
    const int lane = threadIdx.x & 31;
    if (warp >= BATCH) return;

    const int half = lane >> 4;   // which neighbor of the pair this lane gathers
    const int sub  = lane & 15;   // which 32B slice of the 512B row

    // Coalesced load of this node's 32 indices (lane k -> index k). Normal
    // caching: the 12.8MB index array can stay L2-resident across passes.
    long long my_idx;
    if (g_idx_is64) {
        my_idx = __ldg(&((const long long*)neighs_raw)[(size_t)warp * DEGREE + lane]);
    } else {
        my_idx = (long long)__ldg(&((const int*)neighs_raw)[(size_t)warp * DEGREE + lane]);
    }

    float acc[8] = {0.f, 0.f, 0.f, 0.f, 0.f, 0.f, 0.f, 0.f};

    #pragma unroll 4
    for (int k = 0; k < DEGREE / 2; ++k) {
        const long long idx = __shfl_sync(0xffffffffu, my_idx, 2 * k + half);
        if (idx >= seg_lo && idx < seg_hi) {
            const F8 r = ldg_evict_last_v8(&table[(size_t)idx * D_FEAT + sub * 8]);
            #pragma unroll
            for (int i = 0; i < 8; ++i) acc[i] += r.v[i];
        }
    }

    // Fold halves: lanes l and l^16 hold the same columns, disjoint k-subsets.
    #pragma unroll
    for (int i = 0; i < 8; ++i)
        acc[i] += __shfl_xor_sync(0xffffffffu, acc[i], 16);

    if (half == 0) {
        float* dst = out + (size_t)warp * D_FEAT + sub * 8;
        if (!first) {
            const F8 prev = ldg_evict_last_v8(dst);  // partial sums from prior pass
            #pragma unroll
            for (int i = 0; i < 8; ++i) acc[i] += prev.v[i];
        }
        if (last) {
            const float s = 1.0f / (float)DEGREE;
            #pragma unroll
            for (int i = 0; i < 8; ++i) acc[i] *= s;
        }
        float4 lo = make_float4(acc[0], acc[1], acc[2], acc[3]);
        float4 hi = make_float4(acc[4], acc[5], acc[6], acc[7]);
        ((float4*)dst)[0] = lo;
        ((float4*)dst)[1] = hi;
    }
}

extern "C" void kernel_launch(void* const* d_in, const int* in_sizes, int n_in,
                              void* d_out, int out_size)
{
    const void*  neighs = d_in[0];
    const float* table  = (const float*)d_in[1];
    float*       out    = (float*)d_out;

    detect_idx_dtype<<<1, 1>>>((const unsigned int*)neighs);

    const int blocks = (BATCH + WARPS_PER_BLOCK - 1) / WARPS_PER_BLOCK;
    for (int p = 0; p < NSEG; ++p) {
        mean_agg_pass<<<blocks, THREADS>>>(
            neighs, table, out,
            p * SEG, (p + 1) * SEG,
            (p == 0) ? 1 : 0, (p == NSEG - 1) ? 1 : 0);
    }
}

// round 6
// speedup vs baseline: 1.3071x; 1.3071x over previous
#include <cuda_runtime.h>

// MeanAggregator with in-kernel L2 temporal blocking.
// out[b,:] = mean_k table[neighs[b,k],:], B=50000, K=32, table 500000x128 f32.
//
// Single kernel; each warp owns one node, holds its 32 indices + accumulator in
// registers, and sweeps 8 table segments (32MB each) in order. All blocks sweep
// segments in the same order -> resident waves stay in near-lockstep -> the L2
// working set at any instant is ~1-2 segments (<126MB), so repeat-touches of a
// row (avg 3.2x table-wide) hit L2 instead of DRAM.
// Per segment: warp ballot of in-segment lanes, then bursts of up to 8 compacted
// bits -> 4 independent 256-bit evict_last gathers (2 rows x 16 lanes) for MLP.

#define BATCH   50000
#define DEGREE  32
#define D_FEAT  128
#define WARPS_PER_BLOCK 8
#define THREADS (WARPS_PER_BLOCK * 32)
#define NSEG    8
#define SEG     (500000 / NSEG)
#define FULL    0xffffffffu

__device__ int g_idx_is64;

// int64 indices in [0,500000) have all odd 32-bit words == 0; int32 data has
// random values there (P(128 zeros) ~ 0).
__global__ void detect_idx_dtype(const unsigned int* __restrict__ n32)
{
    bool all_zero = true;
    #pragma unroll
    for (int i = 1; i < 256; i += 2) {
        if (n32[i] != 0u) { all_zero = false; break; }
    }
    g_idx_is64 = all_zero ? 1 : 0;
}

struct F8 { float v[8]; };

__device__ __forceinline__ F8 ldg_evict_last_v8(const float* p)
{
    F8 r;
    asm volatile(
        "ld.global.nc.L2::evict_last.v8.b32 {%0,%1,%2,%3,%4,%5,%6,%7}, [%8];"
        : "=f"(r.v[0]), "=f"(r.v[1]), "=f"(r.v[2]), "=f"(r.v[3]),
          "=f"(r.v[4]), "=f"(r.v[5]), "=f"(r.v[6]), "=f"(r.v[7])
        : "l"(p));
    return r;
}

__device__ __forceinline__ void stg_streaming_v4(float4* p, float4 v)
{
    asm volatile("st.global.cs.v4.f32 [%0], {%1,%2,%3,%4};"
                 :: "l"(p), "f"(v.x), "f"(v.y), "f"(v.z), "f"(v.w)
                 : "memory");
}

__global__ __launch_bounds__(THREADS)
void mean_agg_kernel(const void* __restrict__ neighs_raw,
                     const float* __restrict__ table,   // [500000, 128] f32
                     float4* __restrict__ out)          // [50000, 32] float4
{
    const int warp = (blockIdx.x * THREADS + threadIdx.x) >> 5;
    const int lane = threadIdx.x & 31;
    if (warp >= BATCH) return;

    const int half = lane >> 4;   // which row of a gathered pair this lane serves
    const int sub  = lane & 15;   // which 32B slice of the 512B row

    // Coalesced one-time load of this node's 32 indices (lane k -> index k).
    long long my_idx;
    if (g_idx_is64) {
        my_idx = __ldcs(&((const long long*)neighs_raw)[(size_t)warp * DEGREE + lane]);
    } else {
        my_idx = (long long)__ldcs(&((const int*)neighs_raw)[(size_t)warp * DEGREE + lane]);
    }

    float acc[8] = {0.f, 0.f, 0.f, 0.f, 0.f, 0.f, 0.f, 0.f};

    #pragma unroll 1
    for (int p = 0; p < NSEG; ++p) {
        const long long lo = (long long)p * SEG;
        const long long hi = lo + SEG;
        unsigned m = __ballot_sync(FULL, my_idx >= lo && my_idx < hi);

        while (m) {
            // Compact up to 8 set bits -> 4 paired gathers (MLP=4).
            int b[8];
            #pragma unroll
            for (int j = 0; j < 8; ++j) {
                b[j] = m ? (__ffs(m) - 1) : -1;
                m &= (m - 1);
            }

            F8 r[4];
            bool val[4];
            #pragma unroll
            for (int j = 0; j < 4; ++j) {
                const int src = half ? b[2 * j + 1] : b[2 * j];
                val[j] = (src >= 0);
                const long long idx =
                    __shfl_sync(FULL, my_idx, val[j] ? src : 0);
                if (val[j])
                    r[j] = ldg_evict_last_v8(&table[(size_t)idx * D_FEAT + sub * 8]);
            }
            #pragma unroll
            for (int j = 0; j < 4; ++j) {
                if (val[j]) {
                    #pragma unroll
                    for (int i = 0; i < 8; ++i) acc[i] += r[j].v[i];
                }
            }
        }
    }

    // Fold halves: lanes l and l^16 hold the same columns, disjoint neighbor sets.
    #pragma unroll
    for (int i = 0; i < 8; ++i)
        acc[i] += __shfl_xor_sync(FULL, acc[i], 16);

    if (half == 0) {
        const float s = 1.0f / (float)DEGREE;
        float4 v0 = make_float4(acc[0] * s, acc[1] * s, acc[2] * s, acc[3] * s);
        float4 v1 = make_float4(acc[4] * s, acc[5] * s, acc[6] * s, acc[7] * s);
        float4* dst = &out[(size_t)warp * (D_FEAT / 4) + sub * 2];
        stg_streaming_v4(dst, v0);
        stg_streaming_v4(dst + 1, v1);
    }
}

extern "C" void kernel_launch(void* const* d_in, const int* in_sizes, int n_in,
                              void* d_out, int out_size)
{
    const void*  neighs = d_in[0];
    const float* table  = (const float*)d_in[1];
    float4*      out    = (float4*)d_out;

    detect_idx_dtype<<<1, 1>>>((const unsigned int*)neighs);

    const int blocks = (BATCH + WARPS_PER_BLOCK - 1) / WARPS_PER_BLOCK;
    mean_agg_kernel<<<blocks, THREADS>>>(neighs, table, out);
}